// round 16
// baseline (speedup 1.0000x reference)
#include <cuda_runtime.h>
#include <cuda_fp16.h>
#include <math.h>
#include <stdint.h>

#define B_    4
#define NTOK  16384
#define C_    256
#define BN_   65536
#define NQB   256                 // qkgram blocks (256 tokens each)
#define CPB   64                  // chunks per batch = NQB / B_

// ---------------- static device scratch ----------------
__device__ __half g_v[BN_ * C_];
__device__ __half g_Wt[3 * C_ * C_];
__device__ __half g_Mt[B_ * C_ * C_];
__device__ float g_gram_part[NQB * 8 * 32 * 32];
__device__ float g_ssq_part[NQB * C_];
__device__ float g_ssk_part[NQB * C_];

__device__ __forceinline__ void mma_f16(float* c, const uint32_t* a, const uint32_t* b) {
    asm volatile(
        "mma.sync.aligned.m16n8k16.row.col.f32.f16.f16.f32 "
        "{%0,%1,%2,%3}, {%4,%5,%6,%7}, {%8,%9}, {%0,%1,%2,%3};"
        : "+f"(c[0]), "+f"(c[1]), "+f"(c[2]), "+f"(c[3])
        : "r"(a[0]), "r"(a[1]), "r"(a[2]), "r"(a[3]), "r"(b[0]), "r"(b[1]));
}
__device__ __forceinline__ void cp16(void* s, const void* g) {
    uint32_t sa = (uint32_t)__cvta_generic_to_shared(s);
    asm volatile("cp.async.cg.shared.global [%0], [%1], 16;" :: "r"(sa), "l"(g));
}
#define CP_COMMIT() asm volatile("cp.async.commit_group;" ::: "memory")
#define CP_WAIT(n)  asm volatile("cp.async.wait_group %0;" :: "n"(n) : "memory")

__device__ __forceinline__ void ldsm4t(uint32_t* r, const __half* p) {
    uint32_t a = (uint32_t)__cvta_generic_to_shared(p);
    asm volatile("ldmatrix.sync.aligned.m8n8.x4.trans.shared.b16 {%0,%1,%2,%3}, [%4];"
                 : "=r"(r[0]), "=r"(r[1]), "=r"(r[2]), "=r"(r[3]) : "r"(a));
}
__device__ __forceinline__ void ldsm2t(uint32_t* r, const __half* p) {
    uint32_t a = (uint32_t)__cvta_generic_to_shared(p);
    asm volatile("ldmatrix.sync.aligned.m8n8.x2.trans.shared.b16 {%0,%1}, [%2];"
                 : "=r"(r[0]), "=r"(r[1]) : "r"(a));
}
__device__ __forceinline__ void ldsm4(uint32_t* r, const __half* p) {
    uint32_t a = (uint32_t)__cvta_generic_to_shared(p);
    asm volatile("ldmatrix.sync.aligned.m8n8.x4.shared.b16 {%0,%1,%2,%3}, [%4];"
                 : "=r"(r[0]), "=r"(r[1]), "=r"(r[2]), "=r"(r[3]) : "r"(a));
}
__device__ __forceinline__ void ldsm2(uint32_t* r, const __half* p) {
    uint32_t a = (uint32_t)__cvta_generic_to_shared(p);
    asm volatile("ldmatrix.sync.aligned.m8n8.x2.shared.b16 {%0,%1}, [%2];"
                 : "=r"(r[0]), "=r"(r[1]) : "r"(a));
}

#define KC   16
#define SPH  24
#define RS   264

// ---- qkgram smem layout ----
#define KT_OFF  (128 * RS)
#define AH_OFF  (2 * 128 * RS * 2)
#define BH_OFF  (AH_OFF + 2 * 128 * SPH * 2)
#define QKG_SMEM (BH_OFF + 4 * 256 * SPH * 2)    // 196608

// ---- conv/attn merged kernel smem ----
#define CONV_SMEM (51200 + 41472)                // 92672

// ldmatrix per-thread address offsets (in halves), given warp tile origin
// A (m16k16 row-major): row = wm + mf*16 + (lane&7) + ((lane>>3)&1)*8, col = (lane>>4)*8
// B (k16n8, n-major rows): row = wn + nf*8 + (lane&7), col = ((lane>>3)&1)*8
#define AOFF(wm0, lane) (((wm0) + ((lane) & 7) + (((lane) >> 3) & 1) * 8) * SPH + ((lane) >> 4) * 8)
#define BOFF(wn0, lane) (((wn0) + ((lane) & 7)) * SPH + (((lane) >> 3) & 1) * 8)

// projection pass: tile[128x256 fp16 smem] = A[128x256 fp32] @ Bt^T
__device__ __forceinline__ void proj_pass(
    const float* __restrict__ Asrc, const __half* __restrict__ Bt,
    __half* tile, __half* Ah, __half* Bh, int t, float* nacc)
{
    const int warp = t >> 5, lane = t & 31;
    const int wm0 = (warp & 1) * 64, wn0 = (warp >> 1) * 32;
    const int g = lane >> 2, q = lane & 3;
    const int ar = t >> 2, ak4 = (t & 3) * 4;
    const int br = t >> 1, bk = (t & 1) * 8;
    const float* Ab = Asrc + (size_t)ar * 256 + ak4;
    const __half* Bb = Bt + (size_t)br * 256 + bk;
    const int aoff = AOFF(wm0, lane);
    const int boff = BOFF(wn0, lane);

    float acc[4][4][4];
#pragma unroll
    for (int mf = 0; mf < 4; mf++)
#pragma unroll
        for (int nf = 0; nf < 4; nf++)
#pragma unroll
            for (int r = 0; r < 4; r++) acc[mf][nf][r] = 0.f;

    cp16(Bh + 0 * (256 * SPH) + br * SPH + bk, Bb);
    CP_COMMIT();
    cp16(Bh + 1 * (256 * SPH) + br * SPH + bk, Bb + KC);
    CP_COMMIT();
    cp16(Bh + 2 * (256 * SPH) + br * SPH + bk, Bb + 2 * KC);
    CP_COMMIT();
    {
        float4 p0 = *(const float4*)(Ab);
        __half2 h[2];
        h[0] = __float22half2_rn(make_float2(p0.x, p0.y));
        h[1] = __float22half2_rn(make_float2(p0.z, p0.w));
        *(uint2*)&Ah[ar * SPH + ak4] = *(const uint2*)h;
    }
    float4 par0 = *(const float4*)(Ab + KC);
    float4 par1 = *(const float4*)(Ab + 2 * KC);

    for (int c = 0; c < 16; c++) {
        if (c <= 13)      { CP_WAIT(2); }
        else if (c == 14) { CP_WAIT(1); }
        else              { CP_WAIT(0); }
        __syncthreads();
        if (c < 15) {
            __half2 h[2];
            h[0] = __float22half2_rn(make_float2(par0.x, par0.y));
            h[1] = __float22half2_rn(make_float2(par0.z, par0.w));
            *(uint2*)&Ah[((c + 1) & 1) * (128 * SPH) + ar * SPH + ak4] = *(const uint2*)h;
            par0 = par1;
        }
        if (c + 3 < 16) {
            par1 = *(const float4*)(Ab + (c + 3) * KC);
            cp16(Bh + ((c + 3) & 3) * (256 * SPH) + br * SPH + bk, Bb + (c + 3) * KC);
            CP_COMMIT();
        }

        const __half* As = Ah + (c & 1) * (128 * SPH);
        const __half* Bs = Bh + (c & 3) * (256 * SPH);

        uint32_t bf[4][2];
#pragma unroll
        for (int nf = 0; nf < 4; nf++)
            ldsm2(bf[nf], Bs + boff + nf * 8 * SPH);
#pragma unroll
        for (int mf = 0; mf < 4; mf++) {
            uint32_t af[4];
            ldsm4(af, As + aoff + mf * 16 * SPH);
#pragma unroll
            for (int nf = 0; nf < 4; nf++)
                mma_f16(acc[mf][nf], af, bf[nf]);
        }
    }

#pragma unroll
    for (int mf = 0; mf < 4; mf++) {
        int r = wm0 + mf * 16 + g;
#pragma unroll
        for (int nf = 0; nf < 4; nf++) {
            int cb = wn0 + nf * 8 + 2 * q;
            __half2 h2a = __float22half2_rn(make_float2(acc[mf][nf][0], acc[mf][nf][1]));
            __half2 h2b = __float22half2_rn(make_float2(acc[mf][nf][2], acc[mf][nf][3]));
            *(__half2*)&tile[r * RS + cb] = h2a;
            *(__half2*)&tile[(r + 8) * RS + cb] = h2b;
            float2 fa = __half22float2(h2a), fb = __half22float2(h2b);
            nacc[nf * 2 + 0] += fa.x * fa.x + fb.x * fb.x;
            nacc[nf * 2 + 1] += fa.y * fa.y + fb.y * fb.y;
        }
    }
}

// ---------------- qkgram body: 256 tokens per block ----------------
__device__ __forceinline__ void qkgram_body(
    char* smem, int blk, const float* __restrict__ x, const float* __restrict__ y)
{
    __half* qtile = (__half*)smem;
    __half* ktile = qtile + KT_OFF;
    __half* Ah = (__half*)(smem + AH_OFF);
    __half* Bh = (__half*)(smem + BH_OFF);

    const size_t tokbase = (size_t)blk * 256;
    const int t = threadIdx.x;
    const int warp = t >> 5, lane = t & 31;

    const int h = warp >> 1, mi = (warp & 1) * 16;
    const int lrowA = (lane & 7) + ((lane >> 4) << 3);
    const int lcolA = ((lane >> 3) & 1) << 3;
    const int lrowB = (lane & 7) + (((lane >> 3) & 1) << 3);
    float gacc[4][4];
#pragma unroll
    for (int nf = 0; nf < 4; nf++)
#pragma unroll
        for (int r = 0; r < 4; r++) gacc[nf][r] = 0.f;

    float nq8[8], nk8[8];
#pragma unroll
    for (int i = 0; i < 8; i++) { nq8[i] = 0.f; nk8[i] = 0.f; }

    for (int s = 0; s < 2; s++) {
        const size_t tb = (tokbase + s * 128) * 256;
        proj_pass(x + tb, g_Wt, qtile, Ah, Bh, t, nq8);
        proj_pass(y + tb, g_Wt + 65536, ktile, Ah, Bh, t, nk8);
        __syncthreads();

#pragma unroll
        for (int k0 = 0; k0 < 128; k0 += 16) {
            uint32_t af[4];
            ldsm4t(af, &ktile[(k0 + lrowA) * RS + h * 32 + mi + lcolA]);
#pragma unroll
            for (int nf = 0; nf < 4; nf++) {
                uint32_t bf[2];
                ldsm2t(bf, &qtile[(k0 + lrowB) * RS + h * 32 + nf * 8]);
                mma_f16(gacc[nf], af, bf);
            }
        }
        __syncthreads();
    }

    {
        const int g2 = lane >> 2, q2 = lane & 3;
        float* gp = g_gram_part + ((size_t)blk * 8 + h) * 1024;
#pragma unroll
        for (int nf = 0; nf < 4; nf++) {
            int cb = nf * 8 + 2 * q2;
            *(float2*)&gp[(mi + g2) * 32 + cb] = make_float2(gacc[nf][0], gacc[nf][1]);
            *(float2*)&gp[(mi + g2 + 8) * 32 + cb] = make_float2(gacc[nf][2], gacc[nf][3]);
        }
    }

#pragma unroll
    for (int i = 0; i < 8; i++) {
#pragma unroll
        for (int off = 4; off <= 16; off <<= 1) {
            nq8[i] += __shfl_xor_sync(0xffffffffu, nq8[i], off);
            nk8[i] += __shfl_xor_sync(0xffffffffu, nk8[i], off);
        }
    }
    float* nsq = (float*)(smem + AH_OFF);
    float* nsk = nsq + 16 * 32;
    if (lane < 4) {
#pragma unroll
        for (int nf = 0; nf < 4; nf++) {
#pragma unroll
            for (int e = 0; e < 2; e++) {
                nsq[warp * 32 + nf * 8 + 2 * lane + e] = nq8[nf * 2 + e];
                nsk[warp * 32 + nf * 8 + 2 * lane + e] = nk8[nf * 2 + e];
            }
        }
    }
    __syncthreads();
    if (t < 256) {
        int j = t >> 5, loc = t & 31;
        g_ssq_part[(size_t)blk * 256 + t] = nsq[(2 * j) * 32 + loc] + nsq[(2 * j + 1) * 32 + loc];
        g_ssk_part[(size_t)blk * 256 + t] = nsk[(2 * j) * 32 + loc] + nsk[(2 * j + 1) * 32 + loc];
    }
}

// ---------------- gemm_v body ----------------
__device__ __forceinline__ void gemmv_body(char* smem, int vblk, const float* __restrict__ f)
{
    __half* Ah = (__half*)smem;
    __half* Bh = (__half*)(smem + 2 * 128 * SPH * 2);

    const __half* Bt = g_Wt + 2 * 65536;
    __half* C = g_v;
    const int row0 = vblk * 128;

    const int t = threadIdx.x;
    const int warp = t >> 5, lane = t & 31;
    const int wm0 = (warp & 1) * 64, wn0 = (warp >> 1) * 32;
    const int g = lane >> 2, q = lane & 3;
    const int aoff = AOFF(wm0, lane);
    const int boff = BOFF(wn0, lane);

    float acc[4][4][4];
#pragma unroll
    for (int mf = 0; mf < 4; mf++)
#pragma unroll
        for (int nf = 0; nf < 4; nf++)
#pragma unroll
            for (int r = 0; r < 4; r++) acc[mf][nf][r] = 0.f;

    const int ar = t >> 2, ak4 = (t & 3) * 4;
    const float* Ab = f + (size_t)(row0 + ar) * 256 + ak4;
    const int br = t >> 1, bk = (t & 1) * 8;
    const __half* Bb = Bt + (size_t)br * 256 + bk;

    cp16(Bh + 0 * (256 * SPH) + br * SPH + bk, Bb);
    CP_COMMIT();
    cp16(Bh + 1 * (256 * SPH) + br * SPH + bk, Bb + KC);
    CP_COMMIT();
    cp16(Bh + 2 * (256 * SPH) + br * SPH + bk, Bb + 2 * KC);
    CP_COMMIT();
    {
        float4 p0 = *(const float4*)(Ab);
        __half2 h[2];
        h[0] = __float22half2_rn(make_float2(p0.x, p0.y));
        h[1] = __float22half2_rn(make_float2(p0.z, p0.w));
        *(uint2*)&Ah[ar * SPH + ak4] = *(const uint2*)h;
    }
    float4 par0 = *(const float4*)(Ab + KC);
    float4 par1 = *(const float4*)(Ab + 2 * KC);

    for (int c = 0; c < 16; c++) {
        if (c <= 13)      { CP_WAIT(2); }
        else if (c == 14) { CP_WAIT(1); }
        else              { CP_WAIT(0); }
        __syncthreads();
        if (c < 15) {
            __half2 h[2];
            h[0] = __float22half2_rn(make_float2(par0.x, par0.y));
            h[1] = __float22half2_rn(make_float2(par0.z, par0.w));
            *(uint2*)&Ah[((c + 1) & 1) * (128 * SPH) + ar * SPH + ak4] = *(const uint2*)h;
            par0 = par1;
        }
        if (c + 3 < 16) {
            par1 = *(const float4*)(Ab + (c + 3) * KC);
            cp16(Bh + ((c + 3) & 3) * (256 * SPH) + br * SPH + bk, Bb + (c + 3) * KC);
            CP_COMMIT();
        }

        const __half* As = Ah + (c & 1) * (128 * SPH);
        const __half* Bs = Bh + (c & 3) * (256 * SPH);

        uint32_t bf[4][2];
#pragma unroll
        for (int nf = 0; nf < 4; nf++)
            ldsm2(bf[nf], Bs + boff + nf * 8 * SPH);
#pragma unroll
        for (int mf = 0; mf < 4; mf++) {
            uint32_t af[4];
            ldsm4(af, As + aoff + mf * 16 * SPH);
#pragma unroll
            for (int nf = 0; nf < 4; nf++)
                mma_f16(acc[mf][nf], af, bf[nf]);
        }
    }

#pragma unroll
    for (int mf = 0; mf < 4; mf++) {
        int rbase = row0 + wm0 + mf * 16 + g;
#pragma unroll
        for (int nf = 0; nf < 4; nf++) {
            int cb = wn0 + nf * 8 + 2 * q;
            *(__half2*)(C + (size_t)rbase * 256 + cb)
                = __float22half2_rn(make_float2(acc[mf][nf][0], acc[mf][nf][1]));
            *(__half2*)(C + (size_t)(rbase + 8) * 256 + cb)
                = __float22half2_rn(make_float2(acc[mf][nf][2], acc[mf][nf][3]));
        }
    }
}

__global__ void __launch_bounds__(512) k_fused(
    const float* __restrict__ x, const float* __restrict__ y, const float* __restrict__ f)
{
    extern __shared__ char smem[];
    if (blockIdx.x < NQB) qkgram_body(smem, blockIdx.x, x, y);
    else                  gemmv_body(smem, blockIdx.x - NQB, f);
}

// ---- OUT: out += v@Mt + bp (RMW; conv pre-wrote positional branch) ----
__global__ void __launch_bounds__(512) k_gemm_out(
    const float* __restrict__ bp, float* __restrict__ out)
{
    __shared__ __half As4[4][128 * SPH];
    __shared__ __half Bs4[4][256 * SPH];

    const int row0 = blockIdx.x * 128;
    const int b = row0 >> 14;
    const __half* Bt = g_Mt + (size_t)b * 65536;

    const int t = threadIdx.x;
    const int warp = t >> 5, lane = t & 31;
    const int wm0 = (warp & 1) * 64, wn0 = (warp >> 1) * 32;
    const int g = lane >> 2, q = lane & 3;
    const int aoff = AOFF(wm0, lane);
    const int boff = BOFF(wn0, lane);

    float acc[4][4][4];
#pragma unroll
    for (int mf = 0; mf < 4; mf++)
#pragma unroll
        for (int nf = 0; nf < 4; nf++)
#pragma unroll
            for (int r = 0; r < 4; r++) acc[mf][nf][r] = 0.f;

    const int ar = t >> 1, ak = (t & 1) * 8;
    const __half* Ab = g_v + (size_t)(row0 + ar) * 256 + ak;
    const __half* Bb = Bt + (size_t)ar * 256 + ak;

#pragma unroll
    for (int pc = 0; pc < 3; pc++) {
        if (t < 256) cp16(&As4[pc][ar * SPH + ak], Ab + pc * KC);
        cp16(&Bs4[pc][ar * SPH + ak], Bb + pc * KC);
        CP_COMMIT();
    }

    for (int c = 0; c < 16; c++) {
        if (c <= 13)      { CP_WAIT(2); }
        else if (c == 14) { CP_WAIT(1); }
        else              { CP_WAIT(0); }
        __syncthreads();
        if (c + 3 < 16) {
            if (t < 256) cp16(&As4[(c + 3) & 3][ar * SPH + ak], Ab + (c + 3) * KC);
            cp16(&Bs4[(c + 3) & 3][ar * SPH + ak], Bb + (c + 3) * KC);
            CP_COMMIT();
        }
        const __half* As = As4[c & 3];
        const __half* Bs = Bs4[c & 3];

        uint32_t bf[4][2];
#pragma unroll
        for (int nf = 0; nf < 4; nf++)
            ldsm2(bf[nf], Bs + boff + nf * 8 * SPH);
#pragma unroll
        for (int mf = 0; mf < 4; mf++) {
            uint32_t af[4];
            ldsm4(af, As + aoff + mf * 16 * SPH);
#pragma unroll
            for (int nf = 0; nf < 4; nf++)
                mma_f16(acc[mf][nf], af, bf[nf]);
        }
    }

#pragma unroll
    for (int mf = 0; mf < 4; mf++) {
        int rbase = row0 + wm0 + mf * 16 + g;
#pragma unroll
        for (int nf = 0; nf < 4; nf++) {
            int cb = wn0 + nf * 8 + 2 * q;
            float2 bb = *(const float2*)(bp + cb);
            float2* p0 = (float2*)(out + (size_t)rbase * 256 + cb);
            float2* p1 = (float2*)(out + (size_t)(rbase + 8) * 256 + cb);
            float2 o0 = *p0, o1 = *p1;
            o0.x += acc[mf][nf][0] + bb.x; o0.y += acc[mf][nf][1] + bb.y;
            o1.x += acc[mf][nf][2] + bb.x; o1.y += acc[mf][nf][3] + bb.y;
            *p0 = o0;
            *p1 = o1;
        }
    }
}

// =================== weight transpose + fp16 conversion ===================
__global__ void k_wt(const float* __restrict__ Wq, const float* __restrict__ Wk,
                     const float* __restrict__ Wv)
{
    int z = blockIdx.z;
    const float* W = (z == 0) ? Wq : (z == 1) ? Wk : Wv;
    __half* Wt = g_Wt + (size_t)z * 65536;
    __shared__ float tile[32][33];
    int tx = threadIdx.x, ty = threadIdx.y;
    int k0 = blockIdx.y * 32, n0 = blockIdx.x * 32;
#pragma unroll
    for (int i = 0; i < 4; i++)
        tile[ty + 8 * i][tx] = W[(size_t)(k0 + ty + 8 * i) * 256 + n0 + tx];
    __syncthreads();
#pragma unroll
    for (int i = 0; i < 4; i++)
        Wt[(size_t)(n0 + ty + 8 * i) * 256 + k0 + tx] = __float2half_rn(tile[tx][ty + 8 * i]);
}

__device__ __forceinline__ float gelu_exact(float x)
{
    return 0.5f * x * (1.0f + erff(x * 0.7071067811865475f));
}

// ============ attn_m body ============
__device__ __forceinline__ void attn_body(
    char* smem, int bh, const float* __restrict__ Wp, const float* __restrict__ rescale)
{
    int b = bh >> 3, h = bh & 7;
    int t = threadIdx.x;
    float* attn = (float*)smem;
    float* wp = (float*)(smem + 4096);
    float* nq = (float*)(smem + 4096 + 32768);
    float* nk = nq + 32;

#pragma unroll
    for (int s = 0; s < 32; s++) {
        int idx = t + s * 256;
        wp[(idx >> 8) * 256 + (idx & 255)] = Wp[(size_t)(h * 32 + (idx >> 8)) * 256 + (idx & 255)];
    }
    if (t < 32) {
        float sq = 0.f, sk = 0.f;
#pragma unroll
        for (int ch = 0; ch < CPB; ch++) {
            sq += g_ssq_part[(size_t)(b * CPB + ch) * 256 + h * 32 + t];
            sk += g_ssk_part[(size_t)(b * CPB + ch) * 256 + h * 32 + t];
        }
        nq[t] = fmaxf(sqrtf(sq), 1e-12f);
        nk[t] = fmaxf(sqrtf(sk), 1e-12f);
    }
    __syncthreads();

    float resc = rescale[h];
    int w = t >> 5, lane = t & 31;
    for (int i = w; i < 32; i += 8) {
        float g = 0.f;
#pragma unroll
        for (int ch = 0; ch < CPB; ch++)
            g += g_gram_part[((size_t)(b * CPB + ch) * 8 + h) * 1024 + i * 32 + lane];
        float val = g / (nk[i] * nq[lane]) * resc;
        float m = val;
#pragma unroll
        for (int o = 16; o; o >>= 1) m = fmaxf(m, __shfl_xor_sync(0xffffffffu, m, o));
        float e = expf(val - m);
        float ssum = e;
#pragma unroll
        for (int o = 16; o; o >>= 1) ssum += __shfl_xor_sync(0xffffffffu, ssum, o);
        attn[i * 32 + lane] = e / ssum;
    }
    __syncthreads();

    float acc[32];
#pragma unroll
    for (int j = 0; j < 32; j++) acc[j] = 0.f;
#pragma unroll 4
    for (int i = 0; i < 32; i++) {
        float wpv = wp[i * 256 + t];
#pragma unroll
        for (int j = 0; j < 32; j++) acc[j] += attn[i * 32 + j] * wpv;
    }
#pragma unroll
    for (int j = 0; j < 32; j++)
        g_Mt[((size_t)b * 256 + t) * 256 + h * 32 + j] = __float2half_rn(acc[j]);
}

// ============ conv body: 16x16 px, 32 ch (float2); writes fp32 d_out ============
__device__ __forceinline__ void conv_body(
    char* smem, int cid, const float* __restrict__ pw1, const float* __restrict__ pw2,
    float* __restrict__ out)
{
    float2* vs = (float2*)smem;                    // [20][20][16]
    float2* t1 = (float2*)(smem + 51200);          // [18][18][16]

    const int t = threadIdx.x;
    const int cl = t & 15;
    const int tp = t >> 4;
    const int b = cid >> 9;
    const int rem = cid & 511;
    const int chk = rem >> 6;
    const int tile = rem & 63;
    const int c0 = chk * 32 + 2 * cl;
    const int tx0 = (tile & 7) * 16, ty0 = (tile >> 3) * 16;

    float2 w1[9], w2[9];
#pragma unroll
    for (int i = 0; i < 9; i++) {
        w1[i] = *(const float2*)(pw1 + i * 256 + c0);
        w2[i] = *(const float2*)(pw2 + i * 256 + c0);
    }

    for (int p = tp; p < 400; p += 16) {
        int py = p / 20, px = p - py * 20;
        int gy = ty0 + py - 2, gx = tx0 + px - 2;
        float2 v = make_float2(0.f, 0.f);
        if (gy >= 0 && gy < 128 && gx >= 0 && gx < 128) {
            __half2 hv = *(const __half2*)(g_v + (((size_t)(b * 128 + gy)) * 128 + gx) * 256 + c0);
            v = __half22float2(hv);
        }
        vs[(py * 20 + px) * 16 + cl] = v;
    }
    __syncthreads();

    for (int p = tp; p < 324; p += 16) {
        int py = p / 18, px = p - py * 18;
        float2 acc = make_float2(0.f, 0.f);
#pragma unroll
        for (int dy = 0; dy < 3; dy++)
#pragma unroll
            for (int dx = 0; dx < 3; dx++) {
                float2 vv = vs[((py + dy) * 20 + px + dx) * 16 + cl];
                float2 ww = w1[dy * 3 + dx];
                acc.x += vv.x * ww.x;
                acc.y += vv.y * ww.y;
            }
        int gy = ty0 + py - 1, gx = tx0 + px - 1;
        float2 val = make_float2(0.f, 0.f);
        if (gy >= 0 && gy < 128 && gx >= 0 && gx < 128) {
            val.x = gelu_exact(acc.x);
            val.y = gelu_exact(acc.y);
        }
        t1[(py * 18 + px) * 16 + cl] = val;
    }
    __syncthreads();

    for (int p = tp; p < 256; p += 16) {
        int py = p >> 4, px = p & 15;
        float2 acc = make_float2(0.f, 0.f);
#pragma unroll
        for (int dy = 0; dy < 3; dy++)
#pragma unroll
            for (int dx = 0; dx < 3; dx++) {
                float2 vv = t1[((py + dy) * 18 + px + dx) * 16 + cl];
                float2 ww = w2[dy * 3 + dx];
                acc.x += vv.x * ww.x;
                acc.y += vv.y * ww.y;
            }
        *(float2*)(out + (((size_t)(b * 128 + ty0 + py)) * 128 + tx0 + px) * 256 + c0) = acc;
    }
}

__global__ void __launch_bounds__(256) k_conv_attn(
    const float* __restrict__ Wp, const float* __restrict__ rescale,
    const float* __restrict__ pw1, const float* __restrict__ pw2,
    float* __restrict__ out)
{
    extern __shared__ char smem[];
    if (blockIdx.x < 32) attn_body(smem, blockIdx.x, Wp, rescale);
    else                 conv_body(smem, blockIdx.x - 32, pw1, pw2, out);
}

extern "C" void kernel_launch(void* const* d_in, const int* in_sizes, int n_in,
                              void* d_out, int out_size)
{
    const float* x_in    = (const float*)d_in[0];
    const float* y_in    = (const float*)d_in[1];
    const float* f_in    = (const float*)d_in[2];
    const float* Wq      = (const float*)d_in[3];
    const float* Wk      = (const float*)d_in[4];
    const float* Wv      = (const float*)d_in[5];
    const float* rescale = (const float*)d_in[6];
    const float* Wp      = (const float*)d_in[7];
    const float* bp      = (const float*)d_in[8];
    const float* pw1     = (const float*)d_in[9];
    const float* pw2     = (const float*)d_in[10];
    float* out = (float*)d_out;

    cudaFuncSetAttribute(k_fused, cudaFuncAttributeMaxDynamicSharedMemorySize, QKG_SMEM);
    cudaFuncSetAttribute(k_conv_attn, cudaFuncAttributeMaxDynamicSharedMemorySize, CONV_SMEM);

    // 1) transpose + fp16-convert weights
    k_wt<<<dim3(8, 8, 3), dim3(32, 8)>>>(Wq, Wk, Wv);
    // 2) fused: qkgram (256 blocks) + gemm_v (512 blocks)
    k_fused<<<NQB + 512, 512, QKG_SMEM>>>(x_in, y_in, f_in);
    // 3) merged: attn_m (32 blocks) + conv (2048 blocks, writes fp32 d_out)
    k_conv_attn<<<32 + 2048, 256, CONV_SMEM>>>(Wp, rescale, pw1, pw2, out);
    // 4) out += v @ M[b] + bp (RMW)
    k_gemm_out<<<512, 512>>>(bp, out);
}

// round 17
// speedup vs baseline: 1.0163x; 1.0163x over previous
#include <cuda_runtime.h>
#include <cuda_fp16.h>
#include <math.h>
#include <stdint.h>

#define B_    4
#define NTOK  16384
#define C_    256
#define BN_   65536
#define NQB   512                 // qkgram blocks (128 tokens each)
#define CPB   128                 // chunks per batch = NQB / B_

// ---------------- static device scratch ----------------
__device__ __half g_v[BN_ * C_];
__device__ __half g_Wt[3 * C_ * C_];
__device__ __half g_Mt[B_ * C_ * C_];
__device__ float g_gram_part[NQB * 8 * 32 * 32];   // 16 MB
__device__ float g_ssq_part[NQB * C_];
__device__ float g_ssk_part[NQB * C_];

__device__ __forceinline__ void mma_f16(float* c, const uint32_t* a, const uint32_t* b) {
    asm volatile(
        "mma.sync.aligned.m16n8k16.row.col.f32.f16.f16.f32 "
        "{%0,%1,%2,%3}, {%4,%5,%6,%7}, {%8,%9}, {%0,%1,%2,%3};"
        : "+f"(c[0]), "+f"(c[1]), "+f"(c[2]), "+f"(c[3])
        : "r"(a[0]), "r"(a[1]), "r"(a[2]), "r"(a[3]), "r"(b[0]), "r"(b[1]));
}
__device__ __forceinline__ void cp16(void* s, const void* g) {
    uint32_t sa = (uint32_t)__cvta_generic_to_shared(s);
    asm volatile("cp.async.cg.shared.global [%0], [%1], 16;" :: "r"(sa), "l"(g));
}
#define CP_COMMIT() asm volatile("cp.async.commit_group;" ::: "memory")
#define CP_WAIT(n)  asm volatile("cp.async.wait_group %0;" :: "n"(n) : "memory")

__device__ __forceinline__ void ldsm4t(uint32_t* r, const __half* p) {
    uint32_t a = (uint32_t)__cvta_generic_to_shared(p);
    asm volatile("ldmatrix.sync.aligned.m8n8.x4.trans.shared.b16 {%0,%1,%2,%3}, [%4];"
                 : "=r"(r[0]), "=r"(r[1]), "=r"(r[2]), "=r"(r[3]) : "r"(a));
}
__device__ __forceinline__ void ldsm2t(uint32_t* r, const __half* p) {
    uint32_t a = (uint32_t)__cvta_generic_to_shared(p);
    asm volatile("ldmatrix.sync.aligned.m8n8.x2.trans.shared.b16 {%0,%1}, [%2];"
                 : "=r"(r[0]), "=r"(r[1]) : "r"(a));
}
__device__ __forceinline__ void ldsm4(uint32_t* r, const __half* p) {
    uint32_t a = (uint32_t)__cvta_generic_to_shared(p);
    asm volatile("ldmatrix.sync.aligned.m8n8.x4.shared.b16 {%0,%1,%2,%3}, [%4];"
                 : "=r"(r[0]), "=r"(r[1]), "=r"(r[2]), "=r"(r[3]) : "r"(a));
}
__device__ __forceinline__ void ldsm2(uint32_t* r, const __half* p) {
    uint32_t a = (uint32_t)__cvta_generic_to_shared(p);
    asm volatile("ldmatrix.sync.aligned.m8n8.x2.shared.b16 {%0,%1}, [%2];"
                 : "=r"(r[0]), "=r"(r[1]) : "r"(a));
}

#define KC   16
#define SPH  24
#define RS   264

// ---- qkgram smem layout ----
#define KT_OFF  (128 * RS)
#define AH_OFF  (2 * 128 * RS * 2)
#define BH_OFF  (AH_OFF + 2 * 128 * SPH * 2)
#define QKG_SMEM (BH_OFF + 4 * 256 * SPH * 2)    // 196608

// ---- conv/attn merged kernel smem ----
#define CONV_SMEM (51200 + 41472)                // 92672

#define AOFF(wm0, lane) (((wm0) + ((lane) & 7) + (((lane) >> 3) & 1) * 8) * SPH + ((lane) >> 4) * 8)
#define BOFF(wn0, lane) (((wn0) + ((lane) & 7)) * SPH + (((lane) >> 3) & 1) * 8)

// projection pass: tile[128x256 fp16 smem] = A[128x256 fp32] @ Bt^T
__device__ __forceinline__ void proj_pass(
    const float* __restrict__ Asrc, const __half* __restrict__ Bt,
    __half* tile, __half* Ah, __half* Bh, int t, float* nacc)
{
    const int warp = t >> 5, lane = t & 31;
    const int wm0 = (warp & 1) * 64, wn0 = (warp >> 1) * 32;
    const int g = lane >> 2, q = lane & 3;
    const int ar = t >> 2, ak4 = (t & 3) * 4;
    const int br = t >> 1, bk = (t & 1) * 8;
    const float* Ab = Asrc + (size_t)ar * 256 + ak4;
    const __half* Bb = Bt + (size_t)br * 256 + bk;
    const int aoff = AOFF(wm0, lane);
    const int boff = BOFF(wn0, lane);

    float acc[4][4][4];
#pragma unroll
    for (int mf = 0; mf < 4; mf++)
#pragma unroll
        for (int nf = 0; nf < 4; nf++)
#pragma unroll
            for (int r = 0; r < 4; r++) acc[mf][nf][r] = 0.f;

    cp16(Bh + 0 * (256 * SPH) + br * SPH + bk, Bb);
    CP_COMMIT();
    cp16(Bh + 1 * (256 * SPH) + br * SPH + bk, Bb + KC);
    CP_COMMIT();
    cp16(Bh + 2 * (256 * SPH) + br * SPH + bk, Bb + 2 * KC);
    CP_COMMIT();
    {
        float4 p0 = *(const float4*)(Ab);
        __half2 h[2];
        h[0] = __float22half2_rn(make_float2(p0.x, p0.y));
        h[1] = __float22half2_rn(make_float2(p0.z, p0.w));
        *(uint2*)&Ah[ar * SPH + ak4] = *(const uint2*)h;
    }
    float4 par0 = *(const float4*)(Ab + KC);
    float4 par1 = *(const float4*)(Ab + 2 * KC);

    for (int c = 0; c < 16; c++) {
        if (c <= 13)      { CP_WAIT(2); }
        else if (c == 14) { CP_WAIT(1); }
        else              { CP_WAIT(0); }
        __syncthreads();
        if (c < 15) {
            __half2 h[2];
            h[0] = __float22half2_rn(make_float2(par0.x, par0.y));
            h[1] = __float22half2_rn(make_float2(par0.z, par0.w));
            *(uint2*)&Ah[((c + 1) & 1) * (128 * SPH) + ar * SPH + ak4] = *(const uint2*)h;
            par0 = par1;
        }
        if (c + 3 < 16) {
            par1 = *(const float4*)(Ab + (c + 3) * KC);
            cp16(Bh + ((c + 3) & 3) * (256 * SPH) + br * SPH + bk, Bb + (c + 3) * KC);
            CP_COMMIT();
        }

        const __half* As = Ah + (c & 1) * (128 * SPH);
        const __half* Bs = Bh + (c & 3) * (256 * SPH);

        uint32_t bf[4][2];
#pragma unroll
        for (int nf = 0; nf < 4; nf++)
            ldsm2(bf[nf], Bs + boff + nf * 8 * SPH);
#pragma unroll
        for (int mf = 0; mf < 4; mf++) {
            uint32_t af[4];
            ldsm4(af, As + aoff + mf * 16 * SPH);
#pragma unroll
            for (int nf = 0; nf < 4; nf++)
                mma_f16(acc[mf][nf], af, bf[nf]);
        }
    }

#pragma unroll
    for (int mf = 0; mf < 4; mf++) {
        int r = wm0 + mf * 16 + g;
#pragma unroll
        for (int nf = 0; nf < 4; nf++) {
            int cb = wn0 + nf * 8 + 2 * q;
            __half2 h2a = __float22half2_rn(make_float2(acc[mf][nf][0], acc[mf][nf][1]));
            __half2 h2b = __float22half2_rn(make_float2(acc[mf][nf][2], acc[mf][nf][3]));
            *(__half2*)&tile[r * RS + cb] = h2a;
            *(__half2*)&tile[(r + 8) * RS + cb] = h2b;
            float2 fa = __half22float2(h2a), fb = __half22float2(h2b);
            nacc[nf * 2 + 0] += fa.x * fa.x + fb.x * fb.x;
            nacc[nf * 2 + 1] += fa.y * fa.y + fb.y * fb.y;
        }
    }
}

// ---------------- qkgram body: 128 tokens per block ----------------
__device__ __forceinline__ void qkgram_body(
    char* smem, int blk, const float* __restrict__ x, const float* __restrict__ y)
{
    __half* qtile = (__half*)smem;
    __half* ktile = qtile + KT_OFF;
    __half* Ah = (__half*)(smem + AH_OFF);
    __half* Bh = (__half*)(smem + BH_OFF);

    const size_t tb = (size_t)blk * 128 * 256;
    const int t = threadIdx.x;
    const int warp = t >> 5, lane = t & 31;

    const int h = warp >> 1, mi = (warp & 1) * 16;
    const int lrowA = (lane & 7) + ((lane >> 4) << 3);
    const int lcolA = ((lane >> 3) & 1) << 3;
    const int lrowB = (lane & 7) + (((lane >> 3) & 1) << 3);
    float gacc[4][4];
#pragma unroll
    for (int nf = 0; nf < 4; nf++)
#pragma unroll
        for (int r = 0; r < 4; r++) gacc[nf][r] = 0.f;

    float nq8[8], nk8[8];
#pragma unroll
    for (int i = 0; i < 8; i++) { nq8[i] = 0.f; nk8[i] = 0.f; }

    proj_pass(x + tb, g_Wt, qtile, Ah, Bh, t, nq8);
    proj_pass(y + tb, g_Wt + 65536, ktile, Ah, Bh, t, nk8);
    __syncthreads();

#pragma unroll
    for (int k0 = 0; k0 < 128; k0 += 16) {
        uint32_t af[4];
        ldsm4t(af, &ktile[(k0 + lrowA) * RS + h * 32 + mi + lcolA]);
#pragma unroll
        for (int nf = 0; nf < 4; nf++) {
            uint32_t bf[2];
            ldsm2t(bf, &qtile[(k0 + lrowB) * RS + h * 32 + nf * 8]);
            mma_f16(gacc[nf], af, bf);
        }
    }
    __syncthreads();

    {
        const int g2 = lane >> 2, q2 = lane & 3;
        float* gp = g_gram_part + ((size_t)blk * 8 + h) * 1024;
#pragma unroll
        for (int nf = 0; nf < 4; nf++) {
            int cb = nf * 8 + 2 * q2;
            *(float2*)&gp[(mi + g2) * 32 + cb] = make_float2(gacc[nf][0], gacc[nf][1]);
            *(float2*)&gp[(mi + g2 + 8) * 32 + cb] = make_float2(gacc[nf][2], gacc[nf][3]);
        }
    }

#pragma unroll
    for (int i = 0; i < 8; i++) {
#pragma unroll
        for (int off = 4; off <= 16; off <<= 1) {
            nq8[i] += __shfl_xor_sync(0xffffffffu, nq8[i], off);
            nk8[i] += __shfl_xor_sync(0xffffffffu, nk8[i], off);
        }
    }
    float* nsq = (float*)(smem + AH_OFF);
    float* nsk = nsq + 16 * 32;
    if (lane < 4) {
#pragma unroll
        for (int nf = 0; nf < 4; nf++) {
#pragma unroll
            for (int e = 0; e < 2; e++) {
                nsq[warp * 32 + nf * 8 + 2 * lane + e] = nq8[nf * 2 + e];
                nsk[warp * 32 + nf * 8 + 2 * lane + e] = nk8[nf * 2 + e];
            }
        }
    }
    __syncthreads();
    if (t < 256) {
        int j = t >> 5, loc = t & 31;
        g_ssq_part[(size_t)blk * 256 + t] = nsq[(2 * j) * 32 + loc] + nsq[(2 * j + 1) * 32 + loc];
        g_ssk_part[(size_t)blk * 256 + t] = nsk[(2 * j) * 32 + loc] + nsk[(2 * j + 1) * 32 + loc];
    }
}

// ---------------- gemm_v body ----------------
__device__ __forceinline__ void gemmv_body(char* smem, int vblk, const float* __restrict__ f)
{
    __half* Ah = (__half*)smem;
    __half* Bh = (__half*)(smem + 2 * 128 * SPH * 2);

    const __half* Bt = g_Wt + 2 * 65536;
    __half* C = g_v;
    const int row0 = vblk * 128;

    const int t = threadIdx.x;
    const int warp = t >> 5, lane = t & 31;
    const int wm0 = (warp & 1) * 64, wn0 = (warp >> 1) * 32;
    const int g = lane >> 2, q = lane & 3;
    const int aoff = AOFF(wm0, lane);
    const int boff = BOFF(wn0, lane);

    float acc[4][4][4];
#pragma unroll
    for (int mf = 0; mf < 4; mf++)
#pragma unroll
        for (int nf = 0; nf < 4; nf++)
#pragma unroll
            for (int r = 0; r < 4; r++) acc[mf][nf][r] = 0.f;

    const int ar = t >> 2, ak4 = (t & 3) * 4;
    const float* Ab = f + (size_t)(row0 + ar) * 256 + ak4;
    const int br = t >> 1, bk = (t & 1) * 8;
    const __half* Bb = Bt + (size_t)br * 256 + bk;

    cp16(Bh + 0 * (256 * SPH) + br * SPH + bk, Bb);
    CP_COMMIT();
    cp16(Bh + 1 * (256 * SPH) + br * SPH + bk, Bb + KC);
    CP_COMMIT();
    cp16(Bh + 2 * (256 * SPH) + br * SPH + bk, Bb + 2 * KC);
    CP_COMMIT();
    {
        float4 p0 = *(const float4*)(Ab);
        __half2 h[2];
        h[0] = __float22half2_rn(make_float2(p0.x, p0.y));
        h[1] = __float22half2_rn(make_float2(p0.z, p0.w));
        *(uint2*)&Ah[ar * SPH + ak4] = *(const uint2*)h;
    }
    float4 par0 = *(const float4*)(Ab + KC);
    float4 par1 = *(const float4*)(Ab + 2 * KC);

    for (int c = 0; c < 16; c++) {
        if (c <= 13)      { CP_WAIT(2); }
        else if (c == 14) { CP_WAIT(1); }
        else              { CP_WAIT(0); }
        __syncthreads();
        if (c < 15) {
            __half2 h[2];
            h[0] = __float22half2_rn(make_float2(par0.x, par0.y));
            h[1] = __float22half2_rn(make_float2(par0.z, par0.w));
            *(uint2*)&Ah[((c + 1) & 1) * (128 * SPH) + ar * SPH + ak4] = *(const uint2*)h;
            par0 = par1;
        }
        if (c + 3 < 16) {
            par1 = *(const float4*)(Ab + (c + 3) * KC);
            cp16(Bh + ((c + 3) & 3) * (256 * SPH) + br * SPH + bk, Bb + (c + 3) * KC);
            CP_COMMIT();
        }

        const __half* As = Ah + (c & 1) * (128 * SPH);
        const __half* Bs = Bh + (c & 3) * (256 * SPH);

        uint32_t bf[4][2];
#pragma unroll
        for (int nf = 0; nf < 4; nf++)
            ldsm2(bf[nf], Bs + boff + nf * 8 * SPH);
#pragma unroll
        for (int mf = 0; mf < 4; mf++) {
            uint32_t af[4];
            ldsm4(af, As + aoff + mf * 16 * SPH);
#pragma unroll
            for (int nf = 0; nf < 4; nf++)
                mma_f16(acc[mf][nf], af, bf[nf]);
        }
    }

#pragma unroll
    for (int mf = 0; mf < 4; mf++) {
        int rbase = row0 + wm0 + mf * 16 + g;
#pragma unroll
        for (int nf = 0; nf < 4; nf++) {
            int cb = wn0 + nf * 8 + 2 * q;
            *(__half2*)(C + (size_t)rbase * 256 + cb)
                = __float22half2_rn(make_float2(acc[mf][nf][0], acc[mf][nf][1]));
            *(__half2*)(C + (size_t)(rbase + 8) * 256 + cb)
                = __float22half2_rn(make_float2(acc[mf][nf][2], acc[mf][nf][3]));
        }
    }
}

__global__ void __launch_bounds__(512) k_fused(
    const float* __restrict__ x, const float* __restrict__ y, const float* __restrict__ f)
{
    extern __shared__ char smem[];
    if (blockIdx.x < NQB) qkgram_body(smem, blockIdx.x, x, y);
    else                  gemmv_body(smem, blockIdx.x - NQB, f);
}

// ---- OUT: out += v@Mt + bp (RMW; conv pre-wrote positional branch) ----
__global__ void __launch_bounds__(512) k_gemm_out(
    const float* __restrict__ bp, float* __restrict__ out)
{
    __shared__ __half As4[4][128 * SPH];
    __shared__ __half Bs4[4][256 * SPH];

    const int row0 = blockIdx.x * 128;
    const int b = row0 >> 14;
    const __half* Bt = g_Mt + (size_t)b * 65536;

    const int t = threadIdx.x;
    const int warp = t >> 5, lane = t & 31;
    const int wm0 = (warp & 1) * 64, wn0 = (warp >> 1) * 32;
    const int g = lane >> 2, q = lane & 3;
    const int aoff = AOFF(wm0, lane);
    const int boff = BOFF(wn0, lane);

    float acc[4][4][4];
#pragma unroll
    for (int mf = 0; mf < 4; mf++)
#pragma unroll
        for (int nf = 0; nf < 4; nf++)
#pragma unroll
            for (int r = 0; r < 4; r++) acc[mf][nf][r] = 0.f;

    const int ar = t >> 1, ak = (t & 1) * 8;
    const __half* Ab = g_v + (size_t)(row0 + ar) * 256 + ak;
    const __half* Bb = Bt + (size_t)ar * 256 + ak;

#pragma unroll
    for (int pc = 0; pc < 3; pc++) {
        if (t < 256) cp16(&As4[pc][ar * SPH + ak], Ab + pc * KC);
        cp16(&Bs4[pc][ar * SPH + ak], Bb + pc * KC);
        CP_COMMIT();
    }

    for (int c = 0; c < 16; c++) {
        if (c <= 13)      { CP_WAIT(2); }
        else if (c == 14) { CP_WAIT(1); }
        else              { CP_WAIT(0); }
        __syncthreads();
        if (c + 3 < 16) {
            if (t < 256) cp16(&As4[(c + 3) & 3][ar * SPH + ak], Ab + (c + 3) * KC);
            cp16(&Bs4[(c + 3) & 3][ar * SPH + ak], Bb + (c + 3) * KC);
            CP_COMMIT();
        }
        const __half* As = As4[c & 3];
        const __half* Bs = Bs4[c & 3];

        uint32_t bf[4][2];
#pragma unroll
        for (int nf = 0; nf < 4; nf++)
            ldsm2(bf[nf], Bs + boff + nf * 8 * SPH);
#pragma unroll
        for (int mf = 0; mf < 4; mf++) {
            uint32_t af[4];
            ldsm4(af, As + aoff + mf * 16 * SPH);
#pragma unroll
            for (int nf = 0; nf < 4; nf++)
                mma_f16(acc[mf][nf], af, bf[nf]);
        }
    }

#pragma unroll
    for (int mf = 0; mf < 4; mf++) {
        int rbase = row0 + wm0 + mf * 16 + g;
#pragma unroll
        for (int nf = 0; nf < 4; nf++) {
            int cb = wn0 + nf * 8 + 2 * q;
            float2 bb = *(const float2*)(bp + cb);
            float2* p0 = (float2*)(out + (size_t)rbase * 256 + cb);
            float2* p1 = (float2*)(out + (size_t)(rbase + 8) * 256 + cb);
            float2 o0 = *p0, o1 = *p1;
            o0.x += acc[mf][nf][0] + bb.x; o0.y += acc[mf][nf][1] + bb.y;
            o1.x += acc[mf][nf][2] + bb.x; o1.y += acc[mf][nf][3] + bb.y;
            *p0 = o0;
            *p1 = o1;
        }
    }
}

// =================== weight transpose + fp16 conversion ===================
__global__ void k_wt(const float* __restrict__ Wq, const float* __restrict__ Wk,
                     const float* __restrict__ Wv)
{
    int z = blockIdx.z;
    const float* W = (z == 0) ? Wq : (z == 1) ? Wk : Wv;
    __half* Wt = g_Wt + (size_t)z * 65536;
    __shared__ float tile[32][33];
    int tx = threadIdx.x, ty = threadIdx.y;
    int k0 = blockIdx.y * 32, n0 = blockIdx.x * 32;
#pragma unroll
    for (int i = 0; i < 4; i++)
        tile[ty + 8 * i][tx] = W[(size_t)(k0 + ty + 8 * i) * 256 + n0 + tx];
    __syncthreads();
#pragma unroll
    for (int i = 0; i < 4; i++)
        Wt[(size_t)(n0 + ty + 8 * i) * 256 + k0 + tx] = __float2half_rn(tile[tx][ty + 8 * i]);
}

__device__ __forceinline__ float gelu_exact(float x)
{
    return 0.5f * x * (1.0f + erff(x * 0.7071067811865475f));
}

// ============ attn_m body ============
__device__ __forceinline__ void attn_body(
    char* smem, int bh, const float* __restrict__ Wp, const float* __restrict__ rescale)
{
    int b = bh >> 3, h = bh & 7;
    int t = threadIdx.x;
    float* attn = (float*)smem;
    float* wp = (float*)(smem + 4096);
    float* nq = (float*)(smem + 4096 + 32768);
    float* nk = nq + 32;

#pragma unroll
    for (int s = 0; s < 32; s++) {
        int idx = t + s * 256;
        wp[(idx >> 8) * 256 + (idx & 255)] = Wp[(size_t)(h * 32 + (idx >> 8)) * 256 + (idx & 255)];
    }
    if (t < 32) {
        float sq = 0.f, sk = 0.f;
        for (int ch = 0; ch < CPB; ch++) {
            sq += g_ssq_part[(size_t)(b * CPB + ch) * 256 + h * 32 + t];
            sk += g_ssk_part[(size_t)(b * CPB + ch) * 256 + h * 32 + t];
        }
        nq[t] = fmaxf(sqrtf(sq), 1e-12f);
        nk[t] = fmaxf(sqrtf(sk), 1e-12f);
    }
    __syncthreads();

    float resc = rescale[h];
    int w = t >> 5, lane = t & 31;
    for (int i = w; i < 32; i += 8) {
        float g = 0.f;
        for (int ch = 0; ch < CPB; ch++)
            g += g_gram_part[((size_t)(b * CPB + ch) * 8 + h) * 1024 + i * 32 + lane];
        float val = g / (nk[i] * nq[lane]) * resc;
        float m = val;
#pragma unroll
        for (int o = 16; o; o >>= 1) m = fmaxf(m, __shfl_xor_sync(0xffffffffu, m, o));
        float e = expf(val - m);
        float ssum = e;
#pragma unroll
        for (int o = 16; o; o >>= 1) ssum += __shfl_xor_sync(0xffffffffu, ssum, o);
        attn[i * 32 + lane] = e / ssum;
    }
    __syncthreads();

    float acc[32];
#pragma unroll
    for (int j = 0; j < 32; j++) acc[j] = 0.f;
#pragma unroll 4
    for (int i = 0; i < 32; i++) {
        float wpv = wp[i * 256 + t];
#pragma unroll
        for (int j = 0; j < 32; j++) acc[j] += attn[i * 32 + j] * wpv;
    }
#pragma unroll
    for (int j = 0; j < 32; j++)
        g_Mt[((size_t)b * 256 + t) * 256 + h * 32 + j] = __float2half_rn(acc[j]);
}

// ============ conv body: 16x16 px, 32 ch (float2); writes fp32 d_out ============
__device__ __forceinline__ void conv_body(
    char* smem, int cid, const float* __restrict__ pw1, const float* __restrict__ pw2,
    float* __restrict__ out)
{
    float2* vs = (float2*)smem;                    // [20][20][16]
    float2* t1 = (float2*)(smem + 51200);          // [18][18][16]

    const int t = threadIdx.x;
    const int cl = t & 15;
    const int tp = t >> 4;
    const int b = cid >> 9;
    const int rem = cid & 511;
    const int chk = rem >> 6;
    const int tile = rem & 63;
    const int c0 = chk * 32 + 2 * cl;
    const int tx0 = (tile & 7) * 16, ty0 = (tile >> 3) * 16;

    float2 w1[9], w2[9];
#pragma unroll
    for (int i = 0; i < 9; i++) {
        w1[i] = *(const float2*)(pw1 + i * 256 + c0);
        w2[i] = *(const float2*)(pw2 + i * 256 + c0);
    }

    for (int p = tp; p < 400; p += 16) {
        int py = p / 20, px = p - py * 20;
        int gy = ty0 + py - 2, gx = tx0 + px - 2;
        float2 v = make_float2(0.f, 0.f);
        if (gy >= 0 && gy < 128 && gx >= 0 && gx < 128) {
            __half2 hv = *(const __half2*)(g_v + (((size_t)(b * 128 + gy)) * 128 + gx) * 256 + c0);
            v = __half22float2(hv);
        }
        vs[(py * 20 + px) * 16 + cl] = v;
    }
    __syncthreads();

    for (int p = tp; p < 324; p += 16) {
        int py = p / 18, px = p - py * 18;
        float2 acc = make_float2(0.f, 0.f);
#pragma unroll
        for (int dy = 0; dy < 3; dy++)
#pragma unroll
            for (int dx = 0; dx < 3; dx++) {
                float2 vv = vs[((py + dy) * 20 + px + dx) * 16 + cl];
                float2 ww = w1[dy * 3 + dx];
                acc.x += vv.x * ww.x;
                acc.y += vv.y * ww.y;
            }
        int gy = ty0 + py - 1, gx = tx0 + px - 1;
        float2 val = make_float2(0.f, 0.f);
        if (gy >= 0 && gy < 128 && gx >= 0 && gx < 128) {
            val.x = gelu_exact(acc.x);
            val.y = gelu_exact(acc.y);
        }
        t1[(py * 18 + px) * 16 + cl] = val;
    }
    __syncthreads();

    for (int p = tp; p < 256; p += 16) {
        int py = p >> 4, px = p & 15;
        float2 acc = make_float2(0.f, 0.f);
#pragma unroll
        for (int dy = 0; dy < 3; dy++)
#pragma unroll
            for (int dx = 0; dx < 3; dx++) {
                float2 vv = t1[((py + dy) * 18 + px + dx) * 16 + cl];
                float2 ww = w2[dy * 3 + dx];
                acc.x += vv.x * ww.x;
                acc.y += vv.y * ww.y;
            }
        *(float2*)(out + (((size_t)(b * 128 + ty0 + py)) * 128 + tx0 + px) * 256 + c0) = acc;
    }
}

__global__ void __launch_bounds__(256) k_conv_attn(
    const float* __restrict__ Wp, const float* __restrict__ rescale,
    const float* __restrict__ pw1, const float* __restrict__ pw2,
    float* __restrict__ out)
{
    extern __shared__ char smem[];
    if (blockIdx.x < 32) attn_body(smem, blockIdx.x, Wp, rescale);
    else                 conv_body(smem, blockIdx.x - 32, pw1, pw2, out);
}

extern "C" void kernel_launch(void* const* d_in, const int* in_sizes, int n_in,
                              void* d_out, int out_size)
{
    const float* x_in    = (const float*)d_in[0];
    const float* y_in    = (const float*)d_in[1];
    const float* f_in    = (const float*)d_in[2];
    const float* Wq      = (const float*)d_in[3];
    const float* Wk      = (const float*)d_in[4];
    const float* Wv      = (const float*)d_in[5];
    const float* rescale = (const float*)d_in[6];
    const float* Wp      = (const float*)d_in[7];
    const float* bp      = (const float*)d_in[8];
    const float* pw1     = (const float*)d_in[9];
    const float* pw2     = (const float*)d_in[10];
    float* out = (float*)d_out;

    cudaFuncSetAttribute(k_fused, cudaFuncAttributeMaxDynamicSharedMemorySize, QKG_SMEM);
    cudaFuncSetAttribute(k_conv_attn, cudaFuncAttributeMaxDynamicSharedMemorySize, CONV_SMEM);

    // 1) transpose + fp16-convert weights
    k_wt<<<dim3(8, 8, 3), dim3(32, 8)>>>(Wq, Wk, Wv);
    // 2) fused: qkgram (512 blocks @128 tokens) + gemm_v (512 blocks)
    k_fused<<<NQB + 512, 512, QKG_SMEM>>>(x_in, y_in, f_in);
    // 3) merged: attn_m (32 blocks) + conv (2048 blocks, writes fp32 d_out)
    k_conv_attn<<<32 + 2048, 256, CONV_SMEM>>>(Wp, rescale, pw1, pw2, out);
    // 4) out += v @ M[b] + bp (RMW)
    k_gemm_out<<<512, 512>>>(bp, out);
}